// round 1
// baseline (speedup 1.0000x reference)
#include <cuda_runtime.h>

#define DD   256
#define BB   16
#define NN   2048
#define ROWS (BB*NN)

// ---------------- scratch (device globals, no allocation) ----------------
__device__ float g_W[DD*DD];          // Wq @ Wk^T
__device__ float g_u[DD];             // Wk @ bq
__device__ float g_c[ROWS];           // X . u   (per key row)
__device__ float g_A[(size_t)ROWS*DD];    // X @ W
__device__ float g_agg[(size_t)ROWS*DD];  // softmax(S) @ X

// ---------------- W = Wq @ Wk^T  (256 blocks x 256 threads) ----------------
__global__ void k_precomp_W(const float* __restrict__ Wq, const float* __restrict__ Wk) {
    __shared__ float wq[DD];
    int i = blockIdx.x;
    wq[threadIdx.x] = Wq[i*DD + threadIdx.x];
    __syncthreads();
    int j = threadIdx.x;
    const float* wk = Wk + j*DD;
    float s = 0.f;
#pragma unroll 8
    for (int e = 0; e < DD; e++) s += wq[e] * wk[e];
    g_W[i*DD + j] = s;
}

// ---------------- u = Wk @ bq  (1 block x 256 threads) ----------------
__global__ void k_precomp_u(const float* __restrict__ Wk, const float* __restrict__ bq) {
    __shared__ float b[DD];
    b[threadIdx.x] = bq[threadIdx.x];
    __syncthreads();
    int i = threadIdx.x;
    const float* wk = Wk + i*DD;
    float s = 0.f;
#pragma unroll 8
    for (int e = 0; e < DD; e++) s += wk[e] * b[e];
    g_u[i] = s;
}

// ---------------- c[row] = X_row . u  (warp per row) ----------------
__global__ void k_compute_c(const float* __restrict__ X) {
    int warp = (blockIdx.x * blockDim.x + threadIdx.x) >> 5;
    int lane = threadIdx.x & 31;
    if (warp >= ROWS) return;
    const float* x = X + (size_t)warp * DD;
    float s = 0.f;
#pragma unroll
    for (int e = lane; e < DD; e += 32) s += x[e] * g_u[e];
#pragma unroll
    for (int o = 16; o; o >>= 1) s += __shfl_xor_sync(0xffffffffu, s, o);
    if (lane == 0) g_c[warp] = s;
}

// ---------------- generic tiled SGEMM: C[M,256] = A[M,256] @ W[256,256] ----------------
// BM=64, BN=64, BK=16, 256 threads, 4x4 per thread
template<bool RELU, bool BIAS>
__global__ __launch_bounds__(256) void k_sgemm(const float* __restrict__ Ag,
                                               const float* __restrict__ Wg,
                                               const float* __restrict__ bias,
                                               float* __restrict__ Cg) {
    __shared__ float As[16][68];   // transposed [k][m]
    __shared__ float Ws[16][68];   // [k][n]
    int bm = blockIdx.x * 64;
    int bn = blockIdx.y * 64;
    int tid = threadIdx.x;
    int ty = tid >> 4, tx = tid & 15;
    float acc[4][4] = {};
    for (int k0 = 0; k0 < DD; k0 += 16) {
        {   // load A tile 64x16, store transposed
            int row = tid >> 2, kq = tid & 3;
            float4 v = *(const float4*)(Ag + (size_t)(bm + row) * DD + k0 + kq * 4);
            As[kq*4+0][row] = v.x; As[kq*4+1][row] = v.y;
            As[kq*4+2][row] = v.z; As[kq*4+3][row] = v.w;
        }
        {   // load W tile 16x64
            int k = tid >> 4, nq = tid & 15;
            float4 v = *(const float4*)(Wg + (size_t)(k0 + k) * DD + bn + nq * 4);
            *(float4*)&Ws[k][nq*4] = v;
        }
        __syncthreads();
#pragma unroll
        for (int kk = 0; kk < 16; kk++) {
            float a[4], b[4];
#pragma unroll
            for (int i = 0; i < 4; i++) a[i] = As[kk][ty*4 + i];
#pragma unroll
            for (int j = 0; j < 4; j++) b[j] = Ws[kk][tx*4 + j];
#pragma unroll
            for (int i = 0; i < 4; i++)
#pragma unroll
                for (int j = 0; j < 4; j++) acc[i][j] += a[i] * b[j];
        }
        __syncthreads();
    }
#pragma unroll
    for (int i = 0; i < 4; i++) {
        int row = bm + ty*4 + i;
        float4 v;
        v.x = acc[i][0]; v.y = acc[i][1]; v.z = acc[i][2]; v.w = acc[i][3];
        if (BIAS) {
            const float4 bb4 = *(const float4*)(bias + bn + tx*4);
            v.x += bb4.x; v.y += bb4.y; v.z += bb4.z; v.w += bb4.w;
        }
        if (RELU) {
            v.x = fmaxf(v.x, 0.f); v.y = fmaxf(v.y, 0.f);
            v.z = fmaxf(v.z, 0.f); v.w = fmaxf(v.w, 0.f);
        }
        *(float4*)(Cg + (size_t)row * DD + bn + tx*4) = v;
    }
}

// ---------------- fused attention:  agg = softmax(A X^T + c) @ X ----------------
// BM=64 query rows per CTA, BN=64 keys per iteration, D=256 resident.
// K tile == V tile == X tile (one load serves both S and P.V).
#define XS_STRIDE 260   // floats; 16B-aligned rows, breaks worst-case banking
#define PS_STRIDE 68

#define ATTN_SMEM ((2*64*XS_STRIDE + 64*PS_STRIDE + 4*64) * sizeof(float))

__global__ __launch_bounds__(256, 1) void k_attn(const float* __restrict__ X) {
    extern __shared__ float smem[];
    float* As   = smem;                      // [64][XS_STRIDE]
    float* Xs   = As + 64*XS_STRIDE;         // [64][XS_STRIDE]
    float* Ps   = Xs + 64*XS_STRIDE;         // [64][PS_STRIDE]
    float* cs   = Ps + 64*PS_STRIDE;         // [64]
    float* mrun = cs + 64;                   // [64]
    float* lrun = mrun + 64;                 // [64]
    float* alph = lrun + 64;                 // [64]

    int b = blockIdx.y;
    int rowblk = blockIdx.x * 64;
    const float* Xb = X   + (size_t)b * NN * DD;
    const float* Ab = g_A + (size_t)b * NN * DD;
    int tid = threadIdx.x;
    int ty = tid >> 4, tx = tid & 15;

    // load A (query) tile [64][256]
    for (int idx = tid; idx < 64*64; idx += 256) {
        int r = idx >> 6, c4 = idx & 63;
        *(float4*)(As + r*XS_STRIDE + c4*4) =
            *(const float4*)(Ab + (size_t)(rowblk + r) * DD + c4*4);
    }
    if (tid < 64) { mrun[tid] = -1e30f; lrun[tid] = 0.f; }

    float acc[4][16];
#pragma unroll
    for (int i = 0; i < 4; i++)
#pragma unroll
        for (int j = 0; j < 16; j++) acc[i][j] = 0.f;

    for (int kb = 0; kb < NN; kb += 64) {
        __syncthreads();   // previous PV done before overwriting Xs (also covers A load)
        for (int idx = tid; idx < 64*64; idx += 256) {
            int r = idx >> 6, c4 = idx & 63;
            *(float4*)(Xs + r*XS_STRIDE + c4*4) =
                *(const float4*)(Xb + (size_t)(kb + r) * DD + c4*4);
        }
        if (tid < 64) cs[tid] = g_c[b*NN + kb + tid];
        __syncthreads();

        // ---- S tile: rows ty*4+i, cols tx + 16*j ----
        float s[4][4];
#pragma unroll
        for (int i = 0; i < 4; i++)
#pragma unroll
            for (int j = 0; j < 4; j++) s[i][j] = cs[tx + 16*j];

#pragma unroll 2
        for (int d4 = 0; d4 < 64; d4++) {
            float4 a[4], xv[4];
#pragma unroll
            for (int i = 0; i < 4; i++)
                a[i] = *(const float4*)(As + (ty*4 + i)*XS_STRIDE + d4*4);
#pragma unroll
            for (int j = 0; j < 4; j++)
                xv[j] = *(const float4*)(Xs + (tx + 16*j)*XS_STRIDE + d4*4);
#pragma unroll
            for (int i = 0; i < 4; i++)
#pragma unroll
                for (int j = 0; j < 4; j++) {
                    s[i][j] += a[i].x * xv[j].x;
                    s[i][j] += a[i].y * xv[j].y;
                    s[i][j] += a[i].z * xv[j].z;
                    s[i][j] += a[i].w * xv[j].w;
                }
        }
#pragma unroll
        for (int i = 0; i < 4; i++)
#pragma unroll
            for (int j = 0; j < 4; j++)
                Ps[(ty*4 + i)*PS_STRIDE + tx + 16*j] = s[i][j];
        __syncthreads();

        // ---- online softmax row stats (thread per row) ----
        if (tid < 64) {
            float m_old = mrun[tid];
            float mt = m_old;
            float* pr = Ps + tid*PS_STRIDE;
#pragma unroll 8
            for (int k = 0; k < 64; k++) mt = fmaxf(mt, pr[k]);
            float al = __expf(m_old - mt);
            float ls = 0.f;
#pragma unroll 8
            for (int k = 0; k < 64; k++) {
                float p = __expf(pr[k] - mt);
                pr[k] = p;
                ls += p;
            }
            mrun[tid] = mt;
            lrun[tid] = lrun[tid]*al + ls;
            alph[tid] = al;
        }
        __syncthreads();

        // ---- rescale acc ----
#pragma unroll
        for (int i = 0; i < 4; i++) {
            float al = alph[ty*4 + i];
#pragma unroll
            for (int j = 0; j < 16; j++) acc[i][j] *= al;
        }

        // ---- acc += P @ X  (V tile == Xs, already resident) ----
#pragma unroll 4
        for (int k = 0; k < 64; k++) {
            float p[4];
#pragma unroll
            for (int i = 0; i < 4; i++) p[i] = Ps[(ty*4 + i)*PS_STRIDE + k];
            float4 xv[4];
#pragma unroll
            for (int jg = 0; jg < 4; jg++)
                xv[jg] = *(const float4*)(Xs + k*XS_STRIDE + tx*16 + jg*4);
#pragma unroll
            for (int i = 0; i < 4; i++) {
                acc[i][0]  += p[i]*xv[0].x;  acc[i][1]  += p[i]*xv[0].y;
                acc[i][2]  += p[i]*xv[0].z;  acc[i][3]  += p[i]*xv[0].w;
                acc[i][4]  += p[i]*xv[1].x;  acc[i][5]  += p[i]*xv[1].y;
                acc[i][6]  += p[i]*xv[1].z;  acc[i][7]  += p[i]*xv[1].w;
                acc[i][8]  += p[i]*xv[2].x;  acc[i][9]  += p[i]*xv[2].y;
                acc[i][10] += p[i]*xv[2].z;  acc[i][11] += p[i]*xv[2].w;
                acc[i][12] += p[i]*xv[3].x;  acc[i][13] += p[i]*xv[3].y;
                acc[i][14] += p[i]*xv[3].z;  acc[i][15] += p[i]*xv[3].w;
            }
        }
    }

    // ---- normalize + store agg ----
#pragma unroll
    for (int i = 0; i < 4; i++) {
        float inv = 1.f / lrun[ty*4 + i];
        int row = rowblk + ty*4 + i;
        float* dst = g_agg + (size_t)b * NN * DD + (size_t)row * DD + tx*16;
#pragma unroll
        for (int jg = 0; jg < 4; jg++) {
            float4 v;
            v.x = acc[i][jg*4+0]*inv; v.y = acc[i][jg*4+1]*inv;
            v.z = acc[i][jg*4+2]*inv; v.w = acc[i][jg*4+3]*inv;
            *(float4*)(dst + jg*4) = v;
        }
    }
}

// ---------------- launch ----------------
extern "C" void kernel_launch(void* const* d_in, const int* in_sizes, int n_in,
                              void* d_out, int out_size) {
    const float* inp = (const float*)d_in[0];
    const float* Wq  = (const float*)d_in[1];
    const float* bq  = (const float*)d_in[2];
    const float* Wk  = (const float*)d_in[3];
    // bk (d_in[4]) provably drops out of the softmax — unused.
    const float* Wo  = (const float*)d_in[5];
    const float* bo  = (const float*)d_in[6];
    float* out = (float*)d_out;

    float *pW, *pA, *pAgg;
    cudaGetSymbolAddress((void**)&pW,   g_W);
    cudaGetSymbolAddress((void**)&pA,   g_A);
    cudaGetSymbolAddress((void**)&pAgg, g_agg);

    cudaFuncSetAttribute(k_attn, cudaFuncAttributeMaxDynamicSharedMemorySize,
                         (int)ATTN_SMEM);

    k_precomp_W<<<DD, DD>>>(Wq, Wk);
    k_precomp_u<<<1, DD>>>(Wk, bq);
    k_sgemm<false,false><<<dim3(ROWS/64, DD/64), 256>>>(inp, pW, nullptr, pA);
    k_compute_c<<<ROWS/8, 256>>>(inp);
    k_attn<<<dim3(NN/64, BB), 256, ATTN_SMEM>>>(inp);
    k_sgemm<true,true><<<dim3(ROWS/64, DD/64), 256>>>(pAgg, Wo, bo, out);
}

// round 3
// speedup vs baseline: 3.7098x; 3.7098x over previous
#include <cuda_runtime.h>
#include <cuda_bf16.h>
#include <cstdint>

#define DD 256
#define BB 16
#define NN 2048
#define ROWS (BB*NN)

typedef __nv_bfloat16 bf16;

// ------------------------------------------------------------------ scratch
__device__ float g_W[DD*DD];                 // Wq @ Wk^T
__device__ float g_u[DD];                    // Wk @ bq
__device__ float g_c[ROWS];                  // X . u  (per key row)
__device__ float g_invl[ROWS];               // 1 / sum(P)
__device__ float g_S[(size_t)ROWS*NN];       // scores (268MB)

__device__ bf16 g_Xh[(size_t)ROWS*DD],  g_Xl[(size_t)ROWS*DD];    // X splits (row-major)
__device__ bf16 g_Xth[(size_t)BB*DD*NN], g_Xtl[(size_t)BB*DD*NN]; // X^T splits
__device__ bf16 g_Aph[(size_t)ROWS*DD], g_Apl[(size_t)ROWS*DD];   // A' = X@W splits
__device__ bf16 g_Ph[(size_t)ROWS*NN],  g_Pl[(size_t)ROWS*NN];    // softmax splits
__device__ bf16 g_aggh[(size_t)ROWS*DD], g_aggl[(size_t)ROWS*DD]; // agg splits
__device__ bf16 g_Wth[DD*DD], g_Wtl[DD*DD];   // (WqWk^T)^T splits
__device__ bf16 g_Woth[DD*DD], g_Wotl[DD*DD]; // Wo^T splits

// ------------------------------------------------------------------ helpers
__device__ __forceinline__ uint32_t smem_u32(const void* p) {
    uint32_t a;
    asm("{ .reg .u64 t; cvta.to.shared.u64 t, %1; cvt.u32.u64 %0, t; }" : "=r"(a) : "l"(p));
    return a;
}
#define CP16(dst, src) \
    asm volatile("cp.async.cg.shared.global [%0], [%1], 16;" :: "r"(dst), "l"(src))
#define CP_COMMIT() asm volatile("cp.async.commit_group;" ::: "memory")
#define CP_WAIT(n)  asm volatile("cp.async.wait_group %0;" :: "n"(n) : "memory")

#define MMA16816(c, a, b)                                                     \
    asm volatile("mma.sync.aligned.m16n8k16.row.col.f32.bf16.bf16.f32 "       \
        "{%0,%1,%2,%3},{%4,%5,%6,%7},{%8,%9},{%0,%1,%2,%3};"                  \
        : "+f"((c)[0]), "+f"((c)[1]), "+f"((c)[2]), "+f"((c)[3])              \
        : "r"((a)[0]), "r"((a)[1]), "r"((a)[2]), "r"((a)[3]),                 \
          "r"((b)[0]), "r"((b)[1]))

// ------------------------------------------------------------------ small kernels
__global__ void k_precomp_W(const float* __restrict__ Wq, const float* __restrict__ Wk) {
    __shared__ float wq[DD];
    int i = blockIdx.x;
    wq[threadIdx.x] = Wq[i*DD + threadIdx.x];
    __syncthreads();
    int j = threadIdx.x;
    const float* wk = Wk + j*DD;
    float s = 0.f;
#pragma unroll 8
    for (int e = 0; e < DD; e++) s += wq[e] * wk[e];
    g_W[i*DD + j] = s;
}

__global__ void k_precomp_u(const float* __restrict__ Wk, const float* __restrict__ bq) {
    __shared__ float b[DD];
    b[threadIdx.x] = bq[threadIdx.x];
    __syncthreads();
    int i = threadIdx.x;
    const float* wk = Wk + i*DD;
    float s = 0.f;
#pragma unroll 8
    for (int e = 0; e < DD; e++) s += wk[e] * b[e];
    g_u[i] = s;
}

// transpose 256x256 fp32 -> bf16 hi/lo splits (B operand layout [n][k])
__global__ void k_split_w(const float* __restrict__ src, bf16* __restrict__ dh,
                          bf16* __restrict__ dl) {
    int j = blockIdx.x, d = threadIdx.x;
    float f = src[d*DD + j];
    bf16 h = __float2bfloat16(f);
    dh[j*DD + d] = h;
    dl[j*DD + d] = __float2bfloat16(f - __bfloat162float(h));
}

// warp per row: X -> Xh/Xl splits + c = X.u
__global__ void k_splitX(const float* __restrict__ X) {
    __shared__ float us[DD];
    if (threadIdx.x < DD) us[threadIdx.x] = g_u[threadIdx.x];
    __syncthreads();
    int warp = (blockIdx.x * blockDim.x + threadIdx.x) >> 5;
    int lane = threadIdx.x & 31;
    const float* x = X + (size_t)warp * DD;
    float c = 0.f;
#pragma unroll
    for (int i = 0; i < 8; i++) {
        int e = lane + 32*i;
        float f = x[e];
        c += f * us[e];
        bf16 h = __float2bfloat16(f);
        g_Xh[(size_t)warp*DD + e] = h;
        g_Xl[(size_t)warp*DD + e] = __float2bfloat16(f - __bfloat162float(h));
    }
#pragma unroll
    for (int o = 16; o; o >>= 1) c += __shfl_xor_sync(0xffffffffu, c, o);
    if (lane == 0) g_c[warp] = c;
}

// 64x64 tiles: X -> X^T hi/lo splits
__global__ void k_transX(const float* __restrict__ X) {
    __shared__ float t[64][65];
    int n0 = blockIdx.x * 64, d0 = blockIdx.y * 64, b = blockIdx.z;
    const float* Xb = X + (size_t)b * NN * DD;
    int tid = threadIdx.x;
    for (int idx = tid; idx < 64*16; idx += 256) {
        int r = idx >> 4, c4 = idx & 15;
        float4 v = *(const float4*)(Xb + (size_t)(n0 + r)*DD + d0 + c4*4);
        t[r][c4*4+0] = v.x; t[r][c4*4+1] = v.y; t[r][c4*4+2] = v.z; t[r][c4*4+3] = v.w;
    }
    __syncthreads();
    size_t ob = (size_t)b * DD * NN;
    for (int idx = tid; idx < 4096; idx += 256) {
        int r = idx >> 6, c = idx & 63;      // r: d, c: n
        float f = t[c][r];
        bf16 h = __float2bfloat16(f);
        g_Xth[ob + (size_t)(d0 + r)*NN + n0 + c] = h;
        g_Xtl[ob + (size_t)(d0 + r)*NN + n0 + c] = __float2bfloat16(f - __bfloat162float(h));
    }
}

// warp per row softmax: P = exp(S + c - max), l = sum of ROUNDED P splits
__global__ __launch_bounds__(256) void k_softmax() {
    int warp = (blockIdx.x * blockDim.x + threadIdx.x) >> 5;   // row 0..32767
    int lane = threadIdx.x & 31;
    int b = warp >> 11;
    const float* srow = g_S + (size_t)warp * NN;
    const float* crow = g_c + (size_t)b * NN;
    float v[64];
    float mx = -1e30f;
#pragma unroll
    for (int i = 0; i < 64; i++) {
        float s = srow[lane + 32*i] + crow[lane + 32*i];
        v[i] = s;
        mx = fmaxf(mx, s);
    }
#pragma unroll
    for (int o = 16; o; o >>= 1) mx = fmaxf(mx, __shfl_xor_sync(0xffffffffu, mx, o));
    float sum = 0.f;
    size_t ro = (size_t)warp * NN;
#pragma unroll
    for (int i = 0; i < 64; i++) {
        float p = __expf(v[i] - mx);
        bf16 h = __float2bfloat16(p);
        float hv = __bfloat162float(h);
        bf16 l = __float2bfloat16(p - hv);
        g_Ph[ro + lane + 32*i] = h;
        g_Pl[ro + lane + 32*i] = l;
        sum += hv + __bfloat162float(l);
    }
#pragma unroll
    for (int o = 16; o; o >>= 1) sum += __shfl_xor_sync(0xffffffffu, sum, o);
    if (lane == 0) g_invl[warp] = 1.f / sum;
}

// ------------------------------------------------------------------ HMMA GEMM
// C[128,128] tile = sum_k  Ah@Bh^T + Ah@Bl^T + Al@Bh^T
// A:[M,K] row-major hi/lo, B:[N,K] row-major hi/lo (k-major both).
// 8 warps (2x4), warp tile 64x32, mma m16n8k16, BK=32, 2-stage cp.async.

#define TPAD   40                 // bf16 per smem row (32 data + 8 pad) -> 80B
#define TILE_B (128*TPAD*2)       // 10240 bytes per tile
#define OFF_AH 0
#define OFF_AL (1*TILE_B)
#define OFF_BH (2*TILE_B)
#define OFF_BL (3*TILE_B)
#define STAGE_B (4*TILE_B)        // 40960
#define GEMM_SMEM (2*STAGE_B)     // 81920

__device__ __forceinline__ void issue_chunk(
    uint32_t sbase, const bf16* __restrict__ pAh, const bf16* __restrict__ pAl,
    const bf16* __restrict__ pBh, const bf16* __restrict__ pBl,
    int K, int k0, int tid)
{
#pragma unroll
    for (int i = 0; i < 2; i++) {
        int idx = tid + 256*i;
        int row = idx >> 2, seg = idx & 3;
        uint32_t doff = (uint32_t)(row*80 + seg*16);
        size_t goff = (size_t)row*K + k0 + seg*8;
        CP16(sbase + OFF_AH + doff, pAh + goff);
        CP16(sbase + OFF_AL + doff, pAl + goff);
        CP16(sbase + OFF_BH + doff, pBh + goff);
        CP16(sbase + OFF_BL + doff, pBl + goff);
    }
}

// EPI: 0 = fp32   1 = bf16 hi/lo split with optional 1/l row scale   2 = bias+relu fp32
template<int EPI>
__global__ __launch_bounds__(256) void k_gemm(
    const bf16* __restrict__ Ah, const bf16* __restrict__ Al,
    const bf16* __restrict__ Bh, const bf16* __restrict__ Bl,
    float* __restrict__ Cf, bf16* __restrict__ Ch, bf16* __restrict__ Cl,
    const float* __restrict__ bias, const float* __restrict__ invl,
    int K, int ldc, int Mrows, size_t sA, size_t sB, size_t sC)
{
    extern __shared__ char smem[];
    uint32_t sb = smem_u32(smem);
    int tid = threadIdx.x;
    int lane = tid & 31, wid = tid >> 5;
    int g = lane >> 2, t = lane & 3;
    int warp_m = (wid & 1) * 64;
    int warp_n = (wid >> 1) * 32;
    int m0 = blockIdx.x * 128, n0 = blockIdx.y * 128, b = blockIdx.z;

    const bf16* pAh = Ah + (size_t)b*sA + (size_t)m0*K;
    const bf16* pAl = Al + (size_t)b*sA + (size_t)m0*K;
    const bf16* pBh = Bh + (size_t)b*sB + (size_t)n0*K;
    const bf16* pBl = Bl + (size_t)b*sB + (size_t)n0*K;

    float acc[4][4][4];
#pragma unroll
    for (int i = 0; i < 4; i++)
#pragma unroll
        for (int j = 0; j < 4; j++)
#pragma unroll
            for (int r = 0; r < 4; r++) acc[i][j][r] = 0.f;

    int nchunk = K >> 5;
    issue_chunk(sb, pAh, pAl, pBh, pBl, K, 0, tid);
    CP_COMMIT();

    for (int ch = 0; ch < nchunk; ch++) {
        int st = ch & 1;
        if (ch + 1 < nchunk) {
            issue_chunk(sb + (st ^ 1)*STAGE_B, pAh, pAl, pBh, pBl, K, (ch+1) << 5, tid);
            CP_COMMIT();
            CP_WAIT(1);
        } else {
            CP_WAIT(0);
        }
        __syncthreads();

        const char* base = smem + st*STAGE_B;
#pragma unroll
        for (int ks = 0; ks < 2; ks++) {
            int kb = ks * 32;   // byte offset of 16-elem k-step
            uint32_t ah[4][4], al[4][4], bh[4][2], bl[4][2];
#pragma unroll
            for (int i = 0; i < 4; i++) {
                const char* r0 = base + OFF_AH + (warp_m + i*16 + g)*80 + kb + t*4;
                ah[i][0] = *(const uint32_t*)(r0);
                ah[i][1] = *(const uint32_t*)(r0 + 8*80);
                ah[i][2] = *(const uint32_t*)(r0 + 16);
                ah[i][3] = *(const uint32_t*)(r0 + 8*80 + 16);
                const char* r1 = base + OFF_AL + (warp_m + i*16 + g)*80 + kb + t*4;
                al[i][0] = *(const uint32_t*)(r1);
                al[i][1] = *(const uint32_t*)(r1 + 8*80);
                al[i][2] = *(const uint32_t*)(r1 + 16);
                al[i][3] = *(const uint32_t*)(r1 + 8*80 + 16);
            }
#pragma unroll
            for (int j = 0; j < 4; j++) {
                const char* r0 = base + OFF_BH + (warp_n + j*8 + g)*80 + kb + t*4;
                bh[j][0] = *(const uint32_t*)(r0);
                bh[j][1] = *(const uint32_t*)(r0 + 16);
                const char* r1 = base + OFF_BL + (warp_n + j*8 + g)*80 + kb + t*4;
                bl[j][0] = *(const uint32_t*)(r1);
                bl[j][1] = *(const uint32_t*)(r1 + 16);
            }
#pragma unroll
            for (int i = 0; i < 4; i++)
#pragma unroll
                for (int j = 0; j < 4; j++) {
                    MMA16816(acc[i][j], ah[i], bh[j]);
                    MMA16816(acc[i][j], ah[i], bl[j]);
                    MMA16816(acc[i][j], al[i], bh[j]);
                }
        }
        __syncthreads();
    }

    // ---- epilogue ----
#pragma unroll
    for (int i = 0; i < 4; i++) {
        int row0 = m0 + warp_m + i*16 + g;
        float sc0 = 1.f, sc1 = 1.f;
        if (EPI == 1 && invl) {
            sc0 = invl[(size_t)b*Mrows + row0];
            sc1 = invl[(size_t)b*Mrows + row0 + 8];
        }
#pragma unroll
        for (int j = 0; j < 4; j++) {
            int col = n0 + warp_n + j*8 + 2*t;
            if (EPI == 0) {
                float* d0 = Cf + (size_t)b*sC + (size_t)row0*ldc + col;
                float* d1 = d0 + 8*ldc;
                *(float2*)d0 = make_float2(acc[i][j][0], acc[i][j][1]);
                *(float2*)d1 = make_float2(acc[i][j][2], acc[i][j][3]);
            } else if (EPI == 1) {
                float v0 = acc[i][j][0]*sc0, v1 = acc[i][j][1]*sc0;
                float v2 = acc[i][j][2]*sc1, v3 = acc[i][j][3]*sc1;
                bf16 h0 = __float2bfloat16(v0), h1 = __float2bfloat16(v1);
                bf16 h2 = __float2bfloat16(v2), h3 = __float2bfloat16(v3);
                size_t o0 = (size_t)b*sC + (size_t)row0*ldc + col;
                size_t o1 = o0 + 8*(size_t)ldc;
                *(__nv_bfloat162*)(Ch + o0) = __halves2bfloat162(h0, h1);
                *(__nv_bfloat162*)(Ch + o1) = __halves2bfloat162(h2, h3);
                *(__nv_bfloat162*)(Cl + o0) = __halves2bfloat162(
                    __float2bfloat16(v0 - __bfloat162float(h0)),
                    __float2bfloat16(v1 - __bfloat162float(h1)));
                *(__nv_bfloat162*)(Cl + o1) = __halves2bfloat162(
                    __float2bfloat16(v2 - __bfloat162float(h2)),
                    __float2bfloat16(v3 - __bfloat162float(h3)));
            } else {
                float b0 = bias[col], b1 = bias[col+1];
                float* d0 = Cf + (size_t)row0*ldc + col;
                float* d1 = d0 + 8*ldc;
                *(float2*)d0 = make_float2(fmaxf(acc[i][j][0]+b0, 0.f),
                                           fmaxf(acc[i][j][1]+b1, 0.f));
                *(float2*)d1 = make_float2(fmaxf(acc[i][j][2]+b0, 0.f),
                                           fmaxf(acc[i][j][3]+b1, 0.f));
            }
        }
    }
}

// ------------------------------------------------------------------ launch
extern "C" void kernel_launch(void* const* d_in, const int* in_sizes, int n_in,
                              void* d_out, int out_size) {
    const float* inp = (const float*)d_in[0];
    const float* Wq  = (const float*)d_in[1];
    const float* bq  = (const float*)d_in[2];
    const float* Wk  = (const float*)d_in[3];
    // bk (d_in[4]) provably drops out of the softmax — unused.
    const float* Wo  = (const float*)d_in[5];
    const float* bo  = (const float*)d_in[6];
    float* out = (float*)d_out;

    float *pW, *pS, *pInvl;
    bf16 *pXh, *pXl, *pXth, *pXtl, *pAph, *pApl, *pPh, *pPl, *pAggh, *pAggl;
    bf16 *pWth, *pWtl, *pWoth, *pWotl;
    cudaGetSymbolAddress((void**)&pW, g_W);
    cudaGetSymbolAddress((void**)&pS, g_S);
    cudaGetSymbolAddress((void**)&pInvl, g_invl);
    cudaGetSymbolAddress((void**)&pXh, g_Xh);   cudaGetSymbolAddress((void**)&pXl, g_Xl);
    cudaGetSymbolAddress((void**)&pXth, g_Xth); cudaGetSymbolAddress((void**)&pXtl, g_Xtl);
    cudaGetSymbolAddress((void**)&pAph, g_Aph); cudaGetSymbolAddress((void**)&pApl, g_Apl);
    cudaGetSymbolAddress((void**)&pPh, g_Ph);   cudaGetSymbolAddress((void**)&pPl, g_Pl);
    cudaGetSymbolAddress((void**)&pAggh, g_aggh); cudaGetSymbolAddress((void**)&pAggl, g_aggl);
    cudaGetSymbolAddress((void**)&pWth, g_Wth); cudaGetSymbolAddress((void**)&pWtl, g_Wtl);
    cudaGetSymbolAddress((void**)&pWoth, g_Woth); cudaGetSymbolAddress((void**)&pWotl, g_Wotl);

    cudaFuncSetAttribute(k_gemm<0>, cudaFuncAttributeMaxDynamicSharedMemorySize, GEMM_SMEM);
    cudaFuncSetAttribute(k_gemm<1>, cudaFuncAttributeMaxDynamicSharedMemorySize, GEMM_SMEM);
    cudaFuncSetAttribute(k_gemm<2>, cudaFuncAttributeMaxDynamicSharedMemorySize, GEMM_SMEM);

    // prep
    k_precomp_W<<<DD, DD>>>(Wq, Wk);
    k_precomp_u<<<1, DD>>>(Wk, bq);
    k_split_w<<<DD, DD>>>(pW, pWth, pWtl);
    k_split_w<<<DD, DD>>>(Wo, pWoth, pWotl);
    k_splitX<<<ROWS/8, 256>>>(inp);
    k_transX<<<dim3(NN/64, DD/64, BB), 256>>>(inp);

    // A' = X @ W  (M=32768, N=256, K=256) -> bf16 splits
    k_gemm<1><<<dim3(ROWS/128, 2, 1), 256, GEMM_SMEM>>>(
        pXh, pXl, pWth, pWtl, nullptr, pAph, pApl, nullptr, nullptr,
        DD, DD, ROWS, 0, 0, 0);

    // S = A' @ X^T  (per batch 2048x2048, K=256) -> fp32
    k_gemm<0><<<dim3(NN/128, NN/128, BB), 256, GEMM_SMEM>>>(
        pAph, pApl, pXh, pXl, pS, nullptr, nullptr, nullptr, nullptr,
        DD, NN, NN, (size_t)NN*DD, (size_t)NN*DD, (size_t)NN*NN);

    // softmax rows -> P splits + 1/l
    k_softmax<<<ROWS/8, 256>>>();

    // agg = (P @ X) / l  (per batch 2048x256, K=2048) -> bf16 splits
    k_gemm<1><<<dim3(NN/128, 2, BB), 256, GEMM_SMEM>>>(
        pPh, pPl, pXth, pXtl, nullptr, pAggh, pAggl, nullptr, pInvl,
        NN, DD, NN, (size_t)NN*NN, (size_t)DD*NN, (size_t)NN*DD);

    // out = relu(agg @ Wo + bo)  (M=32768, N=256, K=256) -> fp32
    k_gemm<2><<<dim3(ROWS/128, 2, 1), 256, GEMM_SMEM>>>(
        pAggh, pAggl, pWoth, pWotl, out, nullptr, nullptr, bo, nullptr,
        DD, DD, ROWS, 0, 0, 0);
}

// round 4
// speedup vs baseline: 4.3872x; 1.1826x over previous
#include <cuda_runtime.h>
#include <cuda_fp16.h>
#include <cstdint>

#define DD 256
#define BB 16
#define NN 2048
#define ROWS (BB*NN)

typedef __half h16;

// ------------------------------------------------------------------ scratch
__device__ float g_W[DD*DD];                 // Wq @ Wk^T
__device__ float g_u[DD];                    // Wk @ bq
__device__ float g_c[ROWS];                  // X . u  (per key row)
__device__ float g_invl[ROWS];               // 1 / sum(Ph)
__device__ float g_S[(size_t)ROWS*NN];       // scores (268MB)

__device__ h16 g_Xh[(size_t)ROWS*DD],  g_Xl[(size_t)ROWS*DD];    // X splits (row-major)
__device__ h16 g_Xth[(size_t)BB*DD*NN], g_Xtl[(size_t)BB*DD*NN]; // X^T splits
__device__ h16 g_Aph[(size_t)ROWS*DD], g_Apl[(size_t)ROWS*DD];   // A' = X@W splits
__device__ h16 g_Ph[(size_t)ROWS*NN];                            // softmax (hi only)
__device__ h16 g_aggh[(size_t)ROWS*DD], g_aggl[(size_t)ROWS*DD]; // agg splits
__device__ h16 g_Wth[DD*DD], g_Wtl[DD*DD];   // (WqWk^T)^T splits
__device__ h16 g_Woth[DD*DD], g_Wotl[DD*DD]; // Wo^T splits

// ------------------------------------------------------------------ helpers
__device__ __forceinline__ uint32_t smem_u32(const void* p) {
    uint32_t a;
    asm("{ .reg .u64 t; cvta.to.shared.u64 t, %1; cvt.u32.u64 %0, t; }" : "=r"(a) : "l"(p));
    return a;
}
#define CP16(dst, src) \
    asm volatile("cp.async.cg.shared.global [%0], [%1], 16;" :: "r"(dst), "l"(src))
#define CP_COMMIT() asm volatile("cp.async.commit_group;" ::: "memory")
#define CP_WAIT(n)  asm volatile("cp.async.wait_group %0;" :: "n"(n) : "memory")

#define MMA16816(c, a, b)                                                     \
    asm volatile("mma.sync.aligned.m16n8k16.row.col.f32.f16.f16.f32 "         \
        "{%0,%1,%2,%3},{%4,%5,%6,%7},{%8,%9},{%0,%1,%2,%3};"                  \
        : "+f"((c)[0]), "+f"((c)[1]), "+f"((c)[2]), "+f"((c)[3])              \
        : "r"((a)[0]), "r"((a)[1]), "r"((a)[2]), "r"((a)[3]),                 \
          "r"((b)[0]), "r"((b)[1]))

__device__ __forceinline__ void split2(float f, h16& h, h16& l) {
    h = __float2half_rn(f);
    l = __float2half_rn(f - __half2float(h));
}

// ------------------------------------------------------------------ precompute: W = Wq@Wk^T, u = Wk@bq
__global__ void k_precomp(const float* __restrict__ Wq, const float* __restrict__ Wk,
                          const float* __restrict__ bq) {
    __shared__ float v[DD];
    int bx = blockIdx.x;
    if (bx < DD) {
        v[threadIdx.x] = Wq[bx*DD + threadIdx.x];
        __syncthreads();
        int j = threadIdx.x;
        const float* wk = Wk + j*DD;
        float s = 0.f;
#pragma unroll 8
        for (int e = 0; e < DD; e++) s += v[e] * wk[e];
        g_W[bx*DD + j] = s;
    } else {
        v[threadIdx.x] = bq[threadIdx.x];
        __syncthreads();
        int i = threadIdx.x;
        const float* wk = Wk + i*DD;
        float s = 0.f;
#pragma unroll 8
        for (int e = 0; e < DD; e++) s += wk[e] * v[e];
        g_u[i] = s;
    }
}

// ------------------------------------------------------------------ fused prep:
//  blocks [0,512): W / Wo transpose+split   [512,4608): X split + c   [4608,6656): X^T split
__global__ __launch_bounds__(256) void k_prep(const float* __restrict__ X,
                                              const float* __restrict__ Wo) {
    __shared__ float t[64][65];
    __shared__ float us[DD];
    int bx = blockIdx.x, tid = threadIdx.x;
    if (bx < 512) {
        int which = bx >> 8, j = bx & 255, d = tid;
        const float* src = which ? Wo : g_W;
        h16* dh = which ? g_Woth : g_Wth;
        h16* dl = which ? g_Wotl : g_Wtl;
        float f = src[d*DD + j];
        split2(f, dh[j*DD + d], dl[j*DD + d]);
    } else if (bx < 4608) {
        if (tid < DD) us[tid] = g_u[tid];
        __syncthreads();
        int warp = (bx - 512)*8 + (tid >> 5);
        int lane = tid & 31;
        const float* x = X + (size_t)warp * DD;
        float c = 0.f;
#pragma unroll
        for (int i = 0; i < 8; i++) {
            int e = lane + 32*i;
            float f = x[e];
            c += f * us[e];
            split2(f, g_Xh[(size_t)warp*DD + e], g_Xl[(size_t)warp*DD + e]);
        }
#pragma unroll
        for (int o = 16; o; o >>= 1) c += __shfl_xor_sync(0xffffffffu, c, o);
        if (lane == 0) g_c[warp] = c;
    } else {
        int idx = bx - 4608;                 // 32 x 4 x 16
        int n0 = (idx & 31) * 64, d0 = ((idx >> 5) & 3) * 64, b = idx >> 7;
        const float* Xb = X + (size_t)b * NN * DD;
        for (int u = tid; u < 64*16; u += 256) {
            int r = u >> 4, c4 = u & 15;
            float4 v = *(const float4*)(Xb + (size_t)(n0 + r)*DD + d0 + c4*4);
            t[r][c4*4+0] = v.x; t[r][c4*4+1] = v.y; t[r][c4*4+2] = v.z; t[r][c4*4+3] = v.w;
        }
        __syncthreads();
        size_t ob = (size_t)b * DD * NN;
        for (int u = tid; u < 4096; u += 256) {
            int r = u >> 6, c = u & 63;      // r: d, c: n
            split2(t[c][r], g_Xth[ob + (size_t)(d0 + r)*NN + n0 + c],
                            g_Xtl[ob + (size_t)(d0 + r)*NN + n0 + c]);
        }
    }
}

// warp per row softmax: Ph = fp16(exp(S + c - max)), invl = 1/sum(fp32(Ph))
__global__ __launch_bounds__(256) void k_softmax() {
    int warp = (blockIdx.x * blockDim.x + threadIdx.x) >> 5;
    int lane = threadIdx.x & 31;
    int b = warp >> 11;
    const float* srow = g_S + (size_t)warp * NN;
    const float* crow = g_c + (size_t)b * NN;
    float v[64];
    float mx = -1e30f;
#pragma unroll
    for (int i = 0; i < 64; i++) {
        float s = srow[lane + 32*i] + crow[lane + 32*i];
        v[i] = s;
        mx = fmaxf(mx, s);
    }
#pragma unroll
    for (int o = 16; o; o >>= 1) mx = fmaxf(mx, __shfl_xor_sync(0xffffffffu, mx, o));
    float sum = 0.f;
    size_t ro = (size_t)warp * NN;
#pragma unroll
    for (int i = 0; i < 64; i++) {
        float p = __expf(v[i] - mx);
        h16 h = __float2half_rn(p);
        g_Ph[ro + lane + 32*i] = h;
        sum += __half2float(h);
    }
#pragma unroll
    for (int o = 16; o; o >>= 1) sum += __shfl_xor_sync(0xffffffffu, sum, o);
    if (lane == 0) g_invl[warp] = 1.f / sum;
}

// ------------------------------------------------------------------ HMMA GEMM
// C tile 128x128 = sum_k combos of fp16 splits.  SKIP_AL: A has hi only (2 combos).
#define TPAD   40
#define TILE_B (128*TPAD*2)
#define OFF_AH 0
#define OFF_AL (1*TILE_B)
#define OFF_BH (2*TILE_B)
#define OFF_BL (3*TILE_B)
#define STAGE_B (4*TILE_B)
#define GEMM_SMEM (2*STAGE_B)

template<bool SKIP_AL>
__device__ __forceinline__ void issue_chunk(
    uint32_t sbase, const h16* __restrict__ pAh, const h16* __restrict__ pAl,
    const h16* __restrict__ pBh, const h16* __restrict__ pBl,
    int K, int k0, int tid)
{
#pragma unroll
    for (int i = 0; i < 2; i++) {
        int idx = tid + 256*i;
        int row = idx >> 2, seg = idx & 3;
        uint32_t doff = (uint32_t)(row*80 + seg*16);
        size_t goff = (size_t)row*K + k0 + seg*8;
        CP16(sbase + OFF_AH + doff, pAh + goff);
        if (!SKIP_AL) CP16(sbase + OFF_AL + doff, pAl + goff);
        CP16(sbase + OFF_BH + doff, pBh + goff);
        CP16(sbase + OFF_BL + doff, pBl + goff);
    }
}

// EPI: 0 = fp32   1 = fp16 hi/lo split with optional 1/l row scale   2 = bias+relu fp32
template<int EPI, bool SKIP_AL>
__global__ __launch_bounds__(256) void k_gemm(
    const h16* __restrict__ Ah, const h16* __restrict__ Al,
    const h16* __restrict__ Bh, const h16* __restrict__ Bl,
    float* __restrict__ Cf, h16* __restrict__ Ch, h16* __restrict__ Cl,
    const float* __restrict__ bias, const float* __restrict__ invl,
    int K, int ldc, int Mrows, size_t sA, size_t sB, size_t sC)
{
    extern __shared__ char smem[];
    uint32_t sb = smem_u32(smem);
    int tid = threadIdx.x;
    int lane = tid & 31, wid = tid >> 5;
    int g = lane >> 2, t = lane & 3;
    int warp_m = (wid & 1) * 64;
    int warp_n = (wid >> 1) * 32;
    int m0 = blockIdx.x * 128, n0 = blockIdx.y * 128, b = blockIdx.z;

    const h16* pAh = Ah + (size_t)b*sA + (size_t)m0*K;
    const h16* pAl = SKIP_AL ? nullptr : Al + (size_t)b*sA + (size_t)m0*K;
    const h16* pBh = Bh + (size_t)b*sB + (size_t)n0*K;
    const h16* pBl = Bl + (size_t)b*sB + (size_t)n0*K;

    float acc[4][4][4];
#pragma unroll
    for (int i = 0; i < 4; i++)
#pragma unroll
        for (int j = 0; j < 4; j++)
#pragma unroll
            for (int r = 0; r < 4; r++) acc[i][j][r] = 0.f;

    int nchunk = K >> 5;
    issue_chunk<SKIP_AL>(sb, pAh, pAl, pBh, pBl, K, 0, tid);
    CP_COMMIT();

    for (int ch = 0; ch < nchunk; ch++) {
        int st = ch & 1;
        if (ch + 1 < nchunk) {
            issue_chunk<SKIP_AL>(sb + (st ^ 1)*STAGE_B, pAh, pAl, pBh, pBl, K, (ch+1) << 5, tid);
            CP_COMMIT();
            CP_WAIT(1);
        } else {
            CP_WAIT(0);
        }
        __syncthreads();

        const char* base = smem + st*STAGE_B;
#pragma unroll
        for (int ks = 0; ks < 2; ks++) {
            int kb = ks * 32;
            uint32_t ah[4][4], al[4][4], bh[4][2], bl[4][2];
#pragma unroll
            for (int i = 0; i < 4; i++) {
                const char* r0 = base + OFF_AH + (warp_m + i*16 + g)*80 + kb + t*4;
                ah[i][0] = *(const uint32_t*)(r0);
                ah[i][1] = *(const uint32_t*)(r0 + 8*80);
                ah[i][2] = *(const uint32_t*)(r0 + 16);
                ah[i][3] = *(const uint32_t*)(r0 + 8*80 + 16);
                if (!SKIP_AL) {
                    const char* r1 = base + OFF_AL + (warp_m + i*16 + g)*80 + kb + t*4;
                    al[i][0] = *(const uint32_t*)(r1);
                    al[i][1] = *(const uint32_t*)(r1 + 8*80);
                    al[i][2] = *(const uint32_t*)(r1 + 16);
                    al[i][3] = *(const uint32_t*)(r1 + 8*80 + 16);
                }
            }
#pragma unroll
            for (int j = 0; j < 4; j++) {
                const char* r0 = base + OFF_BH + (warp_n + j*8 + g)*80 + kb + t*4;
                bh[j][0] = *(const uint32_t*)(r0);
                bh[j][1] = *(const uint32_t*)(r0 + 16);
                const char* r1 = base + OFF_BL + (warp_n + j*8 + g)*80 + kb + t*4;
                bl[j][0] = *(const uint32_t*)(r1);
                bl[j][1] = *(const uint32_t*)(r1 + 16);
            }
#pragma unroll
            for (int i = 0; i < 4; i++)
#pragma unroll
                for (int j = 0; j < 4; j++) {
                    MMA16816(acc[i][j], ah[i], bh[j]);
                    MMA16816(acc[i][j], ah[i], bl[j]);
                    if (!SKIP_AL) MMA16816(acc[i][j], al[i], bh[j]);
                }
        }
        __syncthreads();
    }

    // ---- epilogue ----
#pragma unroll
    for (int i = 0; i < 4; i++) {
        int row0 = m0 + warp_m + i*16 + g;
        float sc0 = 1.f, sc1 = 1.f;
        if (EPI == 1 && invl) {
            sc0 = invl[(size_t)b*Mrows + row0];
            sc1 = invl[(size_t)b*Mrows + row0 + 8];
        }
#pragma unroll
        for (int j = 0; j < 4; j++) {
            int col = n0 + warp_n + j*8 + 2*t;
            if (EPI == 0) {
                float* d0 = Cf + (size_t)b*sC + (size_t)row0*ldc + col;
                float* d1 = d0 + 8*ldc;
                *(float2*)d0 = make_float2(acc[i][j][0], acc[i][j][1]);
                *(float2*)d1 = make_float2(acc[i][j][2], acc[i][j][3]);
            } else if (EPI == 1) {
                float v0 = acc[i][j][0]*sc0, v1 = acc[i][j][1]*sc0;
                float v2 = acc[i][j][2]*sc1, v3 = acc[i][j][3]*sc1;
                h16 h0, l0, h1, l1, h2, l2, h3, l3;
                split2(v0, h0, l0); split2(v1, h1, l1);
                split2(v2, h2, l2); split2(v3, h3, l3);
                size_t o0 = (size_t)b*sC + (size_t)row0*ldc + col;
                size_t o1 = o0 + 8*(size_t)ldc;
                *(__half2*)(Ch + o0) = __halves2half2(h0, h1);
                *(__half2*)(Ch + o1) = __halves2half2(h2, h3);
                *(__half2*)(Cl + o0) = __halves2half2(l0, l1);
                *(__half2*)(Cl + o1) = __halves2half2(l2, l3);
            } else {
                float b0 = bias[col], b1 = bias[col+1];
                float* d0 = Cf + (size_t)row0*ldc + col;
                float* d1 = d0 + 8*ldc;
                *(float2*)d0 = make_float2(fmaxf(acc[i][j][0]+b0, 0.f),
                                           fmaxf(acc[i][j][1]+b1, 0.f));
                *(float2*)d1 = make_float2(fmaxf(acc[i][j][2]+b0, 0.f),
                                           fmaxf(acc[i][j][3]+b1, 0.f));
            }
        }
    }
}

// ------------------------------------------------------------------ launch
extern "C" void kernel_launch(void* const* d_in, const int* in_sizes, int n_in,
                              void* d_out, int out_size) {
    const float* inp = (const float*)d_in[0];
    const float* Wq  = (const float*)d_in[1];
    const float* bq  = (const float*)d_in[2];
    const float* Wk  = (const float*)d_in[3];
    // bk (d_in[4]) provably drops out of the softmax — unused.
    const float* Wo  = (const float*)d_in[5];
    const float* bo  = (const float*)d_in[6];
    float* out = (float*)d_out;

    float *pS, *pInvl;
    h16 *pXh, *pXl, *pXth, *pXtl, *pAph, *pApl, *pPh, *pAggh, *pAggl;
    h16 *pWth, *pWtl, *pWoth, *pWotl;
    cudaGetSymbolAddress((void**)&pS, g_S);
    cudaGetSymbolAddress((void**)&pInvl, g_invl);
    cudaGetSymbolAddress((void**)&pXh, g_Xh);   cudaGetSymbolAddress((void**)&pXl, g_Xl);
    cudaGetSymbolAddress((void**)&pXth, g_Xth); cudaGetSymbolAddress((void**)&pXtl, g_Xtl);
    cudaGetSymbolAddress((void**)&pAph, g_Aph); cudaGetSymbolAddress((void**)&pApl, g_Apl);
    cudaGetSymbolAddress((void**)&pPh, g_Ph);
    cudaGetSymbolAddress((void**)&pAggh, g_aggh); cudaGetSymbolAddress((void**)&pAggl, g_aggl);
    cudaGetSymbolAddress((void**)&pWth, g_Wth); cudaGetSymbolAddress((void**)&pWtl, g_Wtl);
    cudaGetSymbolAddress((void**)&pWoth, g_Woth); cudaGetSymbolAddress((void**)&pWotl, g_Wotl);

    cudaFuncSetAttribute((const void*)k_gemm<0,false>, cudaFuncAttributeMaxDynamicSharedMemorySize, GEMM_SMEM);
    cudaFuncSetAttribute((const void*)k_gemm<1,false>, cudaFuncAttributeMaxDynamicSharedMemorySize, GEMM_SMEM);
    cudaFuncSetAttribute((const void*)k_gemm<1,true>,  cudaFuncAttributeMaxDynamicSharedMemorySize, GEMM_SMEM);
    cudaFuncSetAttribute((const void*)k_gemm<2,false>, cudaFuncAttributeMaxDynamicSharedMemorySize, GEMM_SMEM);

    // 1) W = Wq Wk^T, u = Wk bq
    k_precomp<<<DD + 1, DD>>>(Wq, Wk, bq);
    // 2) all splits/transposes + c
    k_prep<<<6656, 256>>>(inp, Wo);
    // 3) A' = X @ W -> fp16 splits
    k_gemm<1,false><<<dim3(ROWS/128, 2, 1), 256, GEMM_SMEM>>>(
        pXh, pXl, pWth, pWtl, nullptr, pAph, pApl, nullptr, nullptr,
        DD, DD, ROWS, 0, 0, 0);
    // 4) S = A' @ X^T  (per batch 2048x2048, K=256) -> fp32   [ncu-profiled slot]
    k_gemm<0,false><<<dim3(NN/128, NN/128, BB), 256, GEMM_SMEM>>>(
        pAph, pApl, pXh, pXl, pS, nullptr, nullptr, nullptr, nullptr,
        DD, NN, NN, (size_t)NN*DD, (size_t)NN*DD, (size_t)NN*NN);
    // 5) softmax -> Ph + 1/l
    k_softmax<<<ROWS/8, 256>>>();
    // 6) agg = (Ph @ X) / l  (K=2048, A hi-only: 2 combos) -> fp16 splits
    k_gemm<1,true><<<dim3(NN/128, 2, BB), 256, GEMM_SMEM>>>(
        pPh, nullptr, pXth, pXtl, nullptr, pAggh, pAggl, nullptr, pInvl,
        NN, DD, NN, (size_t)NN*NN, (size_t)DD*NN, (size_t)NN*DD);
    // 7) out = relu(agg @ Wo + bo) -> fp32
    k_gemm<2,false><<<dim3(ROWS/128, 2, 1), 256, GEMM_SMEM>>>(
        pAggh, pAggl, pWoth, pWotl, out, nullptr, nullptr, bo, nullptr,
        DD, DD, ROWS, 0, 0, 0);
}